// round 10
// baseline (speedup 1.0000x reference)
#include <cuda_runtime.h>
#include <cuda_fp16.h>
#include <cstdint>
#include <cstddef>

// ---------------------------------------------------------------------------
// Problem constants (B=4, H=W=64, C=1024)
// ---------------------------------------------------------------------------
#define BB 4
#define NN 4096            // H*W
#define CC 1024
#define ROWB 4096          // bytes/row in g_X: [u(1024 fp16) | hi(1024 fp16)]
#define KITERS 32          // 2 phases x 16 chunks; chunk = 64 fp16 = 128 B rows
#define ABYTES (128 * 128) // A tile: 128 rows x 128 B = 16 KB
#define BBYTES (64 * 128)  // B tile:  64 rows x 128 B =  8 KB
#define STGB (ABYTES + BBYTES)   // 24 KB
#define STG 3
#define SMEM_DYN (STG * STGB)    // 72 KB (epilogue reuses: 128*68*4 = 34.8 KB)
#define SPAD 68            // epilogue SMEM row stride (mult of 4 -> 16B rows)
#define JOBS_PER_B 1056    // sum_{i<32} (2i+2)

static const size_t MATCH_OFF = 0;
static const size_t SIM_OFF   = (size_t)BB * NN * NN;
static const size_t THR_OFF   = (size_t)2 * BB * NN * NN;

// ---------------------------------------------------------------------------
// Device scratch (no allocations allowed)
// ---------------------------------------------------------------------------
__device__ __align__(1024) __half g_X[(size_t)BB * NN * (ROWB / 2)];  // 64 MB
__device__ int      g_mask[BB * NN];
__device__ unsigned g_rowmax[BB * NN];
__device__ float    g_thresh[BB];

// ---------------------------------------------------------------------------
// Helpers
// ---------------------------------------------------------------------------
__device__ __forceinline__ uint32_t smem_u32(const void* p) {
    uint32_t a;
    asm("{ .reg .u64 t; cvta.to.shared.u64 t, %1; cvt.u32.u64 %0, t; }" : "=r"(a) : "l"(p));
    return a;
}

#define SWZ(off) ((off) ^ (((off) >> 3) & 0x70))

#define CP16(dst, src) \
    asm volatile("cp.async.cg.shared.global [%0], [%1], 16;" :: "r"(dst), "l"(src))
#define CP_COMMIT() asm volatile("cp.async.commit_group;" ::: "memory")
#define CP_WAIT_1() asm volatile("cp.async.wait_group 1;" ::: "memory")

__device__ __forceinline__ void ldm_x4(uint32_t* r, uint32_t addr) {
    asm volatile("ldmatrix.sync.aligned.m8n8.x4.shared.b16 {%0,%1,%2,%3}, [%4];"
                 : "=r"(r[0]), "=r"(r[1]), "=r"(r[2]), "=r"(r[3]) : "r"(addr));
}

__device__ __forceinline__ void mma_f16(float* c, const uint32_t* a,
                                        uint32_t b0, uint32_t b1) {
    asm volatile(
        "mma.sync.aligned.m16n8k16.row.col.f32.f16.f16.f32 "
        "{%0,%1,%2,%3}, {%4,%5,%6,%7}, {%8,%9}, {%0,%1,%2,%3};"
        : "+f"(c[0]), "+f"(c[1]), "+f"(c[2]), "+f"(c[3])
        : "r"(a[0]), "r"(a[1]), "r"(a[2]), "r"(a[3]), "r"(b0), "r"(b1));
}

// monotone float <-> uint mapping for atomicMax
__device__ __forceinline__ unsigned enc_f(float f) {
    unsigned b = __float_as_uint(f);
    return (b & 0x80000000u) ? ~b : (b | 0x80000000u);
}
__device__ __forceinline__ float dec_f(unsigned u) {
    return (u & 0x80000000u) ? __uint_as_float(u ^ 0x80000000u) : __uint_as_float(~u);
}

// ---------------------------------------------------------------------------
// Kernel 1: mask decode (dtype auto-detect) + per-call scratch init
// ---------------------------------------------------------------------------
__global__ void decode_kernel(const unsigned* __restrict__ mraw) {
    __shared__ int f_float, f_packed;
    int t = threadIdx.x;
    if (t == 0) { f_float = 0; f_packed = 0; }
    __syncthreads();
    for (int i = t; i < 4096; i += 1024) {
        unsigned w = mraw[i];
        if (w == 0x3F800000u) atomicOr(&f_float, 1);
        else if (w & 0xFFFFFF00u) atomicOr(&f_packed, 1);
    }
    __syncthreads();
    if (f_float) {
        const float* f = reinterpret_cast<const float*>(mraw);
        for (int i = t; i < BB * NN; i += 1024) g_mask[i] = (f[i] != 0.0f);
    } else if (f_packed) {
        const unsigned char* c = reinterpret_cast<const unsigned char*>(mraw);
        for (int i = t; i < BB * NN; i += 1024) g_mask[i] = (c[i] != 0);
    } else {
        for (int i = t; i < BB * NN; i += 1024) g_mask[i] = (mraw[i] != 0);
    }
    for (int i = t; i < BB * NN; i += 1024) g_rowmax[i] = 0u;
}

// ---------------------------------------------------------------------------
// Kernel 2: L2-normalize rows; store u = fp16(hi + 256*(x-hi)) and hi = fp16(x)
// ---------------------------------------------------------------------------
__global__ void __launch_bounds__(256) normalize_kernel(const float* __restrict__ emb) {
    int row = blockIdx.x;
    int t = threadIdx.x;
    const float4 v = reinterpret_cast<const float4*>(emb + (size_t)row * CC)[t];
    double ss = (double)v.x * v.x + (double)v.y * v.y + (double)v.z * v.z + (double)v.w * v.w;
    __shared__ double sred[8];
    int lane = t & 31, w = t >> 5;
    for (int o = 16; o; o >>= 1) ss += __shfl_down_sync(0xffffffffu, ss, o);
    if (lane == 0) sred[w] = ss;
    __syncthreads();
    if (t == 0) {
        double tot = 0.0;
        for (int i = 0; i < 8; i++) tot += sred[i];
        sred[0] = tot;
    }
    __syncthreads();
    float nf = fmaxf((float)sqrt(sred[0]), 1e-12f);
    float f0 = v.x / nf, f1 = v.y / nf, f2 = v.z / nf, f3 = v.w / nf;
    __half h0 = __float2half_rn(f0), h1 = __float2half_rn(f1);
    __half h2 = __float2half_rn(f2), h3 = __float2half_rn(f3);
    float hf0 = __half2float(h0), hf1 = __half2float(h1);
    float hf2 = __half2float(h2), hf3 = __half2float(h3);
    __half u0 = __float2half_rn(fmaf(256.f, f0 - hf0, hf0));
    __half u1 = __float2half_rn(fmaf(256.f, f1 - hf1, hf1));
    __half u2 = __float2half_rn(fmaf(256.f, f2 - hf2, hf2));
    __half u3 = __float2half_rn(fmaf(256.f, f3 - hf3, hf3));
    size_t base = (size_t)row * (ROWB / 2);
    __half2* pu = reinterpret_cast<__half2*>(g_X + base);        // u first
    __half2* ph = reinterpret_cast<__half2*>(g_X + base + CC);   // hi second
    pu[t * 2]     = __halves2half2(u0, u1);
    pu[t * 2 + 1] = __halves2half2(u2, u3);
    ph[t * 2]     = __halves2half2(h0, h1);
    ph[t * 2 + 1] = __halves2half2(h2, h3);
}

// ---------------------------------------------------------------------------
// Kernel 3: symmetric fp16 HMMA GEMM, 128x64 tiles, jobs (i, j64), j64 < 2i+2.
//   u-trick: phase0 acc += u·u^T ; acc *= 1/255 ; phase1 acc += hi·hi^T ;
//   epilogue *= 255/256  =>  sim + ~7e-7 residual.
//   Emits direct 128x64 block and transposed 64x128 block (diagonal 64x64
//   straddle double-writes bitwise-identical values - benign).
// ---------------------------------------------------------------------------
__device__ __forceinline__ void load_stage(uint32_t sb, const char* Xa, const char* Xb,
                                           int kk, int tid) {
    uint32_t off = ((kk < 16) ? 0u : 2048u) + (uint32_t)(kk & 15) * 128u;
#pragma unroll
    for (int it = 0; it < 4; ++it) {     // A tile: 1024 x 16B chunks
        int o = tid + it * 256;
        int row = o >> 3;
        int cb = (o & 7) * 16;
        CP16(sb + SWZ((uint32_t)(row * 128 + cb)),
             Xa + (size_t)row * ROWB + off + cb);
    }
#pragma unroll
    for (int it = 0; it < 2; ++it) {     // B tile: 512 x 16B chunks (64 rows)
        int o = tid + it * 256;
        int row = o >> 3;
        int cb = (o & 7) * 16;
        CP16(sb + ABYTES + SWZ((uint32_t)(row * 128 + cb)),
             Xb + (size_t)row * ROWB + off + cb);
    }
}

__global__ void __launch_bounds__(256, 2) gemm_kernel(float* __restrict__ out) {
    extern __shared__ char sm[];
    uint32_t sbase = smem_u32(sm);
    int tid = threadIdx.x, lane = tid & 31, wid = tid >> 5;
    int b = blockIdx.y;
    int p = blockIdx.x;                  // 0..1055
    // job -> (i, j64): cumulative jobs before i is i*(i+1)
    int i = (int)((sqrtf(4.f * (float)p + 1.f) - 1.f) * 0.5f);
    while ((i + 1) * (i + 2) <= p) i++;
    while (i * (i + 1) > p) i--;
    int j = p - i * (i + 1);             // 0 .. 2i+1
    int i0 = i * 128, j0 = j * 64;

    const char* Xa = (const char*)(g_X + ((size_t)(b * NN) + i0) * (ROWB / 2));
    const char* Xb = (const char*)(g_X + ((size_t)(b * NN) + j0) * (ROWB / 2));

    int wm = wid >> 1;          // 0..3  (m: 32-row slice)
    int wn = wid & 1;           // 0..1  (n: 32-col slice)

    float acc[2][4][4];
#pragma unroll
    for (int a = 0; a < 2; a++)
#pragma unroll
        for (int n = 0; n < 4; n++)
#pragma unroll
            for (int q = 0; q < 4; q++) acc[a][n][q] = 0.f;

    load_stage(sbase + 0 * STGB, Xa, Xb, 0, tid); CP_COMMIT();
    load_stage(sbase + 1 * STGB, Xa, Xb, 1, tid); CP_COMMIT();

    for (int k = 0; k < KITERS; k++) {
        CP_WAIT_1();
        __syncthreads();
        if (k + 2 < KITERS)
            load_stage(sbase + ((k + 2) % STG) * STGB, Xa, Xb, k + 2, tid);
        CP_COMMIT();

        uint32_t as = sbase + (k % STG) * STGB;
        uint32_t bs = as + ABYTES;
#pragma unroll
        for (int ks = 0; ks < 4; ks++) {
            int cb = ks * 32 + ((lane >> 4) * 16);
            uint32_t af[2][4];
#pragma unroll
            for (int mi = 0; mi < 2; mi++) {
                int r = wm * 32 + mi * 16 + (lane & 15);
                ldm_x4(af[mi], as + SWZ((uint32_t)(r * 128 + cb)));
            }
            uint32_t bf[4][2];
#pragma unroll
            for (int nj = 0; nj < 2; nj++) {
                int r = wn * 32 + nj * 16 + (lane & 15);
                uint32_t t4[4];
                ldm_x4(t4, bs + SWZ((uint32_t)(r * 128 + cb)));
                bf[2 * nj][0] = t4[0]; bf[2 * nj][1] = t4[2];
                bf[2 * nj + 1][0] = t4[1]; bf[2 * nj + 1][1] = t4[3];
            }
#pragma unroll
            for (int mi = 0; mi < 2; mi++)
#pragma unroll
                for (int nn = 0; nn < 4; nn++)
                    mma_f16(acc[mi][nn], af[mi], bf[nn][0], bf[nn][1]);
        }

        if (k == 15) {      // end of u·u^T phase: acc = u·u^T / 255
#pragma unroll
            for (int mi = 0; mi < 2; mi++)
#pragma unroll
                for (int nn = 0; nn < 4; nn++)
#pragma unroll
                    for (int q = 0; q < 4; q++) acc[mi][nn][q] *= (1.f / 255.f);
        }
    }

    // ---- epilogue: final scale 255/256, stage to SMEM [128][SPAD], emit both
    __syncthreads();
    float* S = (float*)sm;
    const float FIN = 255.f / 256.f;
#pragma unroll
    for (int mi = 0; mi < 2; mi++)
#pragma unroll
        for (int nn = 0; nn < 4; nn++) {
            int m = wm * 32 + mi * 16 + (lane >> 2);
            int n = wn * 32 + nn * 8 + 2 * (lane & 3);
            S[m * SPAD + n]           = acc[mi][nn][0] * FIN;
            S[m * SPAD + n + 1]       = acc[mi][nn][1] * FIN;
            S[(m + 8) * SPAD + n]     = acc[mi][nn][2] * FIN;
            S[(m + 8) * SPAD + n + 1] = acc[mi][nn][3] * FIN;
        }
    __syncthreads();

    const float NEG_INF = __int_as_float(0xff800000);
    const int* cm = g_mask + b * NN;

    // direct: rows block i (128), cols block j64 (64)
    {
        int row = tid >> 1;      // 0..127
        int ch  = tid & 1;       // 32-col half
        int gm = i0 + row;
        float vmax = NEG_INF;
        float* dst = out + SIM_OFF + ((size_t)(b * NN + gm)) * NN + j0 + ch * 32;
#pragma unroll 4
        for (int c = 0; c < 32; c += 4) {
            float4 v = *(const float4*)&S[row * SPAD + ch * 32 + c];
            __stcs((float4*)(dst + c), v);
            int nb = j0 + ch * 32 + c;
            if (!cm[nb])     vmax = fmaxf(vmax, v.x);
            if (!cm[nb + 1]) vmax = fmaxf(vmax, v.y);
            if (!cm[nb + 2]) vmax = fmaxf(vmax, v.z);
            if (!cm[nb + 3]) vmax = fmaxf(vmax, v.w);
        }
        if (cm[gm]) atomicMax(&g_rowmax[b * NN + gm], enc_f(vmax));
    }

    // transposed: rows block j64 (64), cols block i (128) - unconditional
    {
        int rT = tid >> 2;       // 0..63
        int q  = tid & 3;        // 32-col quarter
        int gr = j0 + rT;
        float vmax = NEG_INF;
        float* dst = out + SIM_OFF + ((size_t)(b * NN + gr)) * NN + i0 + q * 32;
#pragma unroll 4
        for (int c = 0; c < 32; c += 4) {
            float4 v;
            v.x = S[(q * 32 + c + 0) * SPAD + rT];
            v.y = S[(q * 32 + c + 1) * SPAD + rT];
            v.z = S[(q * 32 + c + 2) * SPAD + rT];
            v.w = S[(q * 32 + c + 3) * SPAD + rT];
            __stcs((float4*)(dst + c), v);
            int nb = i0 + q * 32 + c;
            if (!cm[nb])     vmax = fmaxf(vmax, v.x);
            if (!cm[nb + 1]) vmax = fmaxf(vmax, v.y);
            if (!cm[nb + 2]) vmax = fmaxf(vmax, v.z);
            if (!cm[nb + 3]) vmax = fmaxf(vmax, v.w);
        }
        if (cm[gr]) atomicMax(&g_rowmax[b * NN + gr], enc_f(vmax));
    }
}

// ---------------------------------------------------------------------------
// Kernel 4: lower-median of ref-row maxima -> thresh
// ---------------------------------------------------------------------------
__global__ void __launch_bounds__(1024) median_kernel(float* __restrict__ out) {
    int b = blockIdx.x;
    int t = threadIdx.x;
    __shared__ float vals[NN];
    __shared__ int cnt;
    __shared__ float result;
    if (t == 0) cnt = 0;
    __syncthreads();
    for (int i = t; i < NN; i += 1024)
        if (g_mask[b * NN + i]) {
            int idx = atomicAdd(&cnt, 1);
            vals[idx] = dec_f(g_rowmax[b * NN + i]);
        }
    __syncthreads();
    int k = cnt;
    int med = (k - 1) >> 1;
    for (int i = t; i < k; i += 1024) {
        float v = vals[i];
        int less = 0, eq = 0;
        for (int jj = 0; jj < k; jj++) {
            float u = vals[jj];
            less += (u < v);
            eq += (u == v);
        }
        if (less <= med && med < less + eq) result = v;
    }
    __syncthreads();
    if (t == 0) {
        g_thresh[b] = result;
        out[THR_OFF + b] = result;
    }
}

// ---------------------------------------------------------------------------
// Kernel 5: match = ref_row & ~ref_col & (sim > thresh)
// ---------------------------------------------------------------------------
__global__ void __launch_bounds__(256) match_kernel(float* __restrict__ out) {
    int bi = blockIdx.x;                  // b*NN + i
    int b = bi >> 12;
    int t = threadIdx.x;
    float* mrow = out + MATCH_OFF + (size_t)bi * NN;
    if (!g_mask[bi]) {
        float4 z = make_float4(0.f, 0.f, 0.f, 0.f);
        for (int c = t; c < NN / 4; c += 256)
            __stcs(reinterpret_cast<float4*>(mrow) + c, z);
        return;
    }
    float th = g_thresh[b];
    const float* srow = out + SIM_OFF + (size_t)bi * NN;
    const int* cmask = g_mask + b * NN;
    for (int c = t; c < NN / 4; c += 256) {
        float4 s = __ldcs(reinterpret_cast<const float4*>(srow) + c);
        int j0 = c * 4;
        float4 r;
        r.x = (cmask[j0 + 0] == 0 && s.x > th) ? 1.f : 0.f;
        r.y = (cmask[j0 + 1] == 0 && s.y > th) ? 1.f : 0.f;
        r.z = (cmask[j0 + 2] == 0 && s.z > th) ? 1.f : 0.f;
        r.w = (cmask[j0 + 3] == 0 && s.w > th) ? 1.f : 0.f;
        __stcs(reinterpret_cast<float4*>(mrow) + c, r);
    }
}

// ---------------------------------------------------------------------------
// Launch
// ---------------------------------------------------------------------------
extern "C" void kernel_launch(void* const* d_in, const int* in_sizes, int n_in,
                              void* d_out, int out_size) {
    const float* emb = (const float*)d_in[0];
    const void* mask = d_in[1];
    if (n_in >= 2 && in_sizes[0] < in_sizes[1]) {
        emb = (const float*)d_in[1];
        mask = d_in[0];
    }
    float* out = (float*)d_out;

    cudaFuncSetAttribute(gemm_kernel, cudaFuncAttributeMaxDynamicSharedMemorySize, SMEM_DYN);

    decode_kernel<<<1, 1024>>>((const unsigned*)mask);
    normalize_kernel<<<BB * NN, 256>>>(emb);
    gemm_kernel<<<dim3(JOBS_PER_B, BB), 256, SMEM_DYN>>>(out);
    median_kernel<<<BB, 1024>>>(out);
    match_kernel<<<BB * NN, 256>>>(out);
}

// round 11
// speedup vs baseline: 1.0823x; 1.0823x over previous
#include <cuda_runtime.h>
#include <cuda_fp16.h>
#include <cstdint>
#include <cstddef>

// ---------------------------------------------------------------------------
// Problem constants (B=4, H=W=64, C=1024)
// ---------------------------------------------------------------------------
#define BB 4
#define NN 4096            // H*W
#define CC 1024
#define ROWB 4096          // bytes/row in g_X: [u(1024 fp16) | hi(1024 fp16)]
#define BM 128
#define KITERS 32          // 2 phases x 16 chunks; chunk = 64 fp16 = 128 B rows
#define ABYTES (BM * 128)  // 16 KB
#define STGB (2 * ABYTES)  // 32 KB (A + B)
#define STG 3
#define SMEM_DYN (STG * STGB)  // 96 KB (epilogue reuses: 128*132*4 = 67.6 KB)
#define SPAD 132           // epilogue SMEM row stride (16B-aligned rows)

static const size_t MATCH_OFF = 0;
static const size_t SIM_OFF   = (size_t)BB * NN * NN;
static const size_t THR_OFF   = (size_t)2 * BB * NN * NN;

// ---------------------------------------------------------------------------
// Device scratch (no allocations allowed)
// ---------------------------------------------------------------------------
__device__ __align__(1024) __half g_X[(size_t)BB * NN * (ROWB / 2)];  // 64 MB
__device__ int      g_mask[BB * NN];
__device__ unsigned g_rowmax[BB * NN];
__device__ float    g_thresh[BB];

// ---------------------------------------------------------------------------
// Helpers
// ---------------------------------------------------------------------------
__device__ __forceinline__ uint32_t smem_u32(const void* p) {
    uint32_t a;
    asm("{ .reg .u64 t; cvta.to.shared.u64 t, %1; cvt.u32.u64 %0, t; }" : "=r"(a) : "l"(p));
    return a;
}

#define SWZ(off) ((off) ^ (((off) >> 3) & 0x70))

#define CP16(dst, src) \
    asm volatile("cp.async.cg.shared.global [%0], [%1], 16;" :: "r"(dst), "l"(src))
#define CP_COMMIT() asm volatile("cp.async.commit_group;" ::: "memory")
#define CP_WAIT_1() asm volatile("cp.async.wait_group 1;" ::: "memory")

__device__ __forceinline__ void ldm_x4(uint32_t* r, uint32_t addr) {
    asm volatile("ldmatrix.sync.aligned.m8n8.x4.shared.b16 {%0,%1,%2,%3}, [%4];"
                 : "=r"(r[0]), "=r"(r[1]), "=r"(r[2]), "=r"(r[3]) : "r"(addr));
}

__device__ __forceinline__ void mma_f16(float* c, const uint32_t* a,
                                        uint32_t b0, uint32_t b1) {
    asm volatile(
        "mma.sync.aligned.m16n8k16.row.col.f32.f16.f16.f32 "
        "{%0,%1,%2,%3}, {%4,%5,%6,%7}, {%8,%9}, {%0,%1,%2,%3};"
        : "+f"(c[0]), "+f"(c[1]), "+f"(c[2]), "+f"(c[3])
        : "r"(a[0]), "r"(a[1]), "r"(a[2]), "r"(a[3]), "r"(b0), "r"(b1));
}

// monotone float <-> uint mapping for atomicMax
__device__ __forceinline__ unsigned enc_f(float f) {
    unsigned b = __float_as_uint(f);
    return (b & 0x80000000u) ? ~b : (b | 0x80000000u);
}
__device__ __forceinline__ float dec_f(unsigned u) {
    return (u & 0x80000000u) ? __uint_as_float(u ^ 0x80000000u) : __uint_as_float(~u);
}

// ---------------------------------------------------------------------------
// Kernel 1: mask decode (dtype auto-detect) + per-call scratch init
// ---------------------------------------------------------------------------
__global__ void decode_kernel(const unsigned* __restrict__ mraw) {
    __shared__ int f_float, f_packed;
    int t = threadIdx.x;
    if (t == 0) { f_float = 0; f_packed = 0; }
    __syncthreads();
    for (int i = t; i < 4096; i += 1024) {
        unsigned w = mraw[i];
        if (w == 0x3F800000u) atomicOr(&f_float, 1);
        else if (w & 0xFFFFFF00u) atomicOr(&f_packed, 1);
    }
    __syncthreads();
    if (f_float) {
        const float* f = reinterpret_cast<const float*>(mraw);
        for (int i = t; i < BB * NN; i += 1024) g_mask[i] = (f[i] != 0.0f);
    } else if (f_packed) {
        const unsigned char* c = reinterpret_cast<const unsigned char*>(mraw);
        for (int i = t; i < BB * NN; i += 1024) g_mask[i] = (c[i] != 0);
    } else {
        for (int i = t; i < BB * NN; i += 1024) g_mask[i] = (mraw[i] != 0);
    }
    for (int i = t; i < BB * NN; i += 1024) g_rowmax[i] = 0u;
}

// ---------------------------------------------------------------------------
// Kernel 2: L2-normalize rows; store u = fp16(hi + 256*(x-hi)) and hi = fp16(x)
// ---------------------------------------------------------------------------
__global__ void __launch_bounds__(256) normalize_kernel(const float* __restrict__ emb) {
    int row = blockIdx.x;
    int t = threadIdx.x;
    const float4 v = reinterpret_cast<const float4*>(emb + (size_t)row * CC)[t];
    double ss = (double)v.x * v.x + (double)v.y * v.y + (double)v.z * v.z + (double)v.w * v.w;
    __shared__ double sred[8];
    int lane = t & 31, w = t >> 5;
    for (int o = 16; o; o >>= 1) ss += __shfl_down_sync(0xffffffffu, ss, o);
    if (lane == 0) sred[w] = ss;
    __syncthreads();
    if (t == 0) {
        double tot = 0.0;
        for (int i = 0; i < 8; i++) tot += sred[i];
        sred[0] = tot;
    }
    __syncthreads();
    float nf = fmaxf((float)sqrt(sred[0]), 1e-12f);
    float f0 = v.x / nf, f1 = v.y / nf, f2 = v.z / nf, f3 = v.w / nf;
    __half h0 = __float2half_rn(f0), h1 = __float2half_rn(f1);
    __half h2 = __float2half_rn(f2), h3 = __float2half_rn(f3);
    float hf0 = __half2float(h0), hf1 = __half2float(h1);
    float hf2 = __half2float(h2), hf3 = __half2float(h3);
    __half u0 = __float2half_rn(fmaf(256.f, f0 - hf0, hf0));
    __half u1 = __float2half_rn(fmaf(256.f, f1 - hf1, hf1));
    __half u2 = __float2half_rn(fmaf(256.f, f2 - hf2, hf2));
    __half u3 = __float2half_rn(fmaf(256.f, f3 - hf3, hf3));
    size_t base = (size_t)row * (ROWB / 2);
    __half2* pu = reinterpret_cast<__half2*>(g_X + base);        // u first
    __half2* ph = reinterpret_cast<__half2*>(g_X + base + CC);   // hi second
    pu[t * 2]     = __halves2half2(u0, u1);
    pu[t * 2 + 1] = __halves2half2(u2, u3);
    ph[t * 2]     = __halves2half2(h0, h1);
    ph[t * 2 + 1] = __halves2half2(h2, h3);
}

// ---------------------------------------------------------------------------
// Kernel 3: symmetric fp16 HMMA GEMM, 128x128 tiles, j <= i.  "u-trick":
//   Phase 0 (chunks 0-15):  acc += u·u^T   | boundary: acc *= 1/255
//   Phase 1 (chunks 16-31): acc += hi·hi^T | epilogue: acc *= 255/256
//   => acc = (255*hi·hi^T + u·u^T)/256 = sim + ~7e-7 residual
//   Emits C[i,j] and C[j,i]^T via SMEM transpose + ref-row maxima.
// ---------------------------------------------------------------------------
__device__ __forceinline__ void load_stage(uint32_t sb, const char* Xa, const char* Xb,
                                           int kk, int tid) {
    uint32_t off = ((kk < 16) ? 0u : 2048u) + (uint32_t)(kk & 15) * 128u;
#pragma unroll
    for (int it = 0; it < 4; ++it) {     // A tile: 1024 x 16B chunks
        int o = tid + it * 256;
        int row = o >> 3;
        int cb = (o & 7) * 16;
        CP16(sb + SWZ((uint32_t)(row * 128 + cb)),
             Xa + (size_t)row * ROWB + off + cb);
    }
#pragma unroll
    for (int it = 0; it < 4; ++it) {     // B tile
        int o = tid + it * 256;
        int row = o >> 3;
        int cb = (o & 7) * 16;
        CP16(sb + ABYTES + SWZ((uint32_t)(row * 128 + cb)),
             Xb + (size_t)row * ROWB + off + cb);
    }
}

__global__ void __launch_bounds__(256, 2) gemm_kernel(float* __restrict__ out) {
    extern __shared__ char sm[];
    uint32_t sbase = smem_u32(sm);
    int tid = threadIdx.x, lane = tid & 31, wid = tid >> 5;
    int b = blockIdx.y;
    int p = blockIdx.x;
    // pair index -> (i, j) with j <= i
    int i = (int)((sqrtf(8.f * (float)p + 1.f) - 1.f) * 0.5f);
    while ((i + 1) * (i + 2) / 2 <= p) i++;
    while (i * (i + 1) / 2 > p) i--;
    int j = p - i * (i + 1) / 2;
    int i0 = i * BM, j0 = j * BM;

    const char* Xa = (const char*)(g_X + ((size_t)(b * NN) + i0) * (ROWB / 2));
    const char* Xb = (const char*)(g_X + ((size_t)(b * NN) + j0) * (ROWB / 2));

    int wm = wid >> 1;          // 0..3  (m: 32-row slice)
    int wn = wid & 1;           // 0..1  (n: 64-col slice)

    float acc[2][8][4];
#pragma unroll
    for (int a = 0; a < 2; a++)
#pragma unroll
        for (int n = 0; n < 8; n++)
#pragma unroll
            for (int q = 0; q < 4; q++) acc[a][n][q] = 0.f;

    load_stage(sbase + 0 * STGB, Xa, Xb, 0, tid); CP_COMMIT();
    load_stage(sbase + 1 * STGB, Xa, Xb, 1, tid); CP_COMMIT();

    for (int k = 0; k < KITERS; k++) {
        CP_WAIT_1();
        __syncthreads();
        if (k + 2 < KITERS)
            load_stage(sbase + ((k + 2) % STG) * STGB, Xa, Xb, k + 2, tid);
        CP_COMMIT();

        uint32_t as = sbase + (k % STG) * STGB;
        uint32_t bs = as + ABYTES;
#pragma unroll
        for (int ks = 0; ks < 4; ks++) {
            int cb = ks * 32 + ((lane >> 4) * 16);
            uint32_t af[2][4];
#pragma unroll
            for (int mi = 0; mi < 2; mi++) {
                int r = wm * 32 + mi * 16 + (lane & 15);
                ldm_x4(af[mi], as + SWZ((uint32_t)(r * 128 + cb)));
            }
            uint32_t bf[8][2];
#pragma unroll
            for (int nj = 0; nj < 4; nj++) {
                int r = wn * 64 + nj * 16 + (lane & 15);
                uint32_t t4[4];
                ldm_x4(t4, bs + SWZ((uint32_t)(r * 128 + cb)));
                bf[2 * nj][0] = t4[0]; bf[2 * nj][1] = t4[2];
                bf[2 * nj + 1][0] = t4[1]; bf[2 * nj + 1][1] = t4[3];
            }
#pragma unroll
            for (int mi = 0; mi < 2; mi++)
#pragma unroll
                for (int nn = 0; nn < 8; nn++)
                    mma_f16(acc[mi][nn], af[mi], bf[nn][0], bf[nn][1]);
        }

        if (k == 15) {      // end of u·u^T phase: acc = u·u^T / 255
#pragma unroll
            for (int mi = 0; mi < 2; mi++)
#pragma unroll
                for (int nn = 0; nn < 8; nn++)
#pragma unroll
                    for (int q = 0; q < 4; q++) acc[mi][nn][q] *= (1.f / 255.f);
        }
    }

    // ---- epilogue: final scale 255/256, stage to SMEM [128][SPAD], emit both
    __syncthreads();
    float* S = (float*)sm;
    const float FIN = 255.f / 256.f;
#pragma unroll
    for (int mi = 0; mi < 2; mi++)
#pragma unroll
        for (int nn = 0; nn < 8; nn++) {
            int m = wm * 32 + mi * 16 + (lane >> 2);
            int n = wn * 64 + nn * 8 + 2 * (lane & 3);
            S[m * SPAD + n]           = acc[mi][nn][0] * FIN;
            S[m * SPAD + n + 1]       = acc[mi][nn][1] * FIN;
            S[(m + 8) * SPAD + n]     = acc[mi][nn][2] * FIN;
            S[(m + 8) * SPAD + n + 1] = acc[mi][nn][3] * FIN;
        }
    __syncthreads();

    const float NEG_INF = __int_as_float(0xff800000);
    const int* cm = g_mask + b * NN;
    int row = tid >> 1;          // 0..127
    int ch  = tid & 1;           // half-row (64 cols)

    // direct: rows block i, cols block j
    {
        int gm = i0 + row;
        float vmax = NEG_INF;
        float* dst = out + SIM_OFF + ((size_t)(b * NN + gm)) * NN + j0 + ch * 64;
#pragma unroll 4
        for (int c = 0; c < 64; c += 4) {
            float4 v = *(const float4*)&S[row * SPAD + ch * 64 + c];
            __stcs((float4*)(dst + c), v);
            int nb = j0 + ch * 64 + c;
            if (!cm[nb])     vmax = fmaxf(vmax, v.x);
            if (!cm[nb + 1]) vmax = fmaxf(vmax, v.y);
            if (!cm[nb + 2]) vmax = fmaxf(vmax, v.z);
            if (!cm[nb + 3]) vmax = fmaxf(vmax, v.w);
        }
        if (cm[gm]) atomicMax(&g_rowmax[b * NN + gm], enc_f(vmax));
    }

    // transposed: rows block j, cols block i
    if (i != j) {
        int gr = j0 + row;
        float vmax = NEG_INF;
        float* dst = out + SIM_OFF + ((size_t)(b * NN + gr)) * NN + i0 + ch * 64;
#pragma unroll 4
        for (int c = 0; c < 64; c += 4) {
            float4 v;
            v.x = S[(ch * 64 + c + 0) * SPAD + row];
            v.y = S[(ch * 64 + c + 1) * SPAD + row];
            v.z = S[(ch * 64 + c + 2) * SPAD + row];
            v.w = S[(ch * 64 + c + 3) * SPAD + row];
            __stcs((float4*)(dst + c), v);
            int nb = i0 + ch * 64 + c;
            if (!cm[nb])     vmax = fmaxf(vmax, v.x);
            if (!cm[nb + 1]) vmax = fmaxf(vmax, v.y);
            if (!cm[nb + 2]) vmax = fmaxf(vmax, v.z);
            if (!cm[nb + 3]) vmax = fmaxf(vmax, v.w);
        }
        if (cm[gr]) atomicMax(&g_rowmax[b * NN + gr], enc_f(vmax));
    }
}

// ---------------------------------------------------------------------------
// Kernel 4: lower-median of ref-row maxima -> thresh
// ---------------------------------------------------------------------------
__global__ void __launch_bounds__(1024) median_kernel(float* __restrict__ out) {
    int b = blockIdx.x;
    int t = threadIdx.x;
    __shared__ float vals[NN];
    __shared__ int cnt;
    __shared__ float result;
    if (t == 0) cnt = 0;
    __syncthreads();
    for (int i = t; i < NN; i += 1024)
        if (g_mask[b * NN + i]) {
            int idx = atomicAdd(&cnt, 1);
            vals[idx] = dec_f(g_rowmax[b * NN + i]);
        }
    __syncthreads();
    int k = cnt;
    int med = (k - 1) >> 1;
    for (int i = t; i < k; i += 1024) {
        float v = vals[i];
        int less = 0, eq = 0;
        for (int jj = 0; jj < k; jj++) {
            float u = vals[jj];
            less += (u < v);
            eq += (u == v);
        }
        if (less <= med && med < less + eq) result = v;
    }
    __syncthreads();
    if (t == 0) {
        g_thresh[b] = result;
        out[THR_OFF + b] = result;
    }
}

// ---------------------------------------------------------------------------
// Kernel 5: match = ref_row & ~ref_col & (sim > thresh)
// ---------------------------------------------------------------------------
__global__ void __launch_bounds__(256) match_kernel(float* __restrict__ out) {
    int bi = blockIdx.x;                  // b*NN + i
    int b = bi >> 12;
    int t = threadIdx.x;
    float* mrow = out + MATCH_OFF + (size_t)bi * NN;
    if (!g_mask[bi]) {
        float4 z = make_float4(0.f, 0.f, 0.f, 0.f);
        for (int c = t; c < NN / 4; c += 256)
            __stcs(reinterpret_cast<float4*>(mrow) + c, z);
        return;
    }
    float th = g_thresh[b];
    const float* srow = out + SIM_OFF + (size_t)bi * NN;
    const int* cmask = g_mask + b * NN;
    for (int c = t; c < NN / 4; c += 256) {
        float4 s = __ldcs(reinterpret_cast<const float4*>(srow) + c);
        int j0 = c * 4;
        float4 r;
        r.x = (cmask[j0 + 0] == 0 && s.x > th) ? 1.f : 0.f;
        r.y = (cmask[j0 + 1] == 0 && s.y > th) ? 1.f : 0.f;
        r.z = (cmask[j0 + 2] == 0 && s.z > th) ? 1.f : 0.f;
        r.w = (cmask[j0 + 3] == 0 && s.w > th) ? 1.f : 0.f;
        __stcs(reinterpret_cast<float4*>(mrow) + c, r);
    }
}

// ---------------------------------------------------------------------------
// Launch  (R8 config minus the noop launches)
// ---------------------------------------------------------------------------
extern "C" void kernel_launch(void* const* d_in, const int* in_sizes, int n_in,
                              void* d_out, int out_size) {
    const float* emb = (const float*)d_in[0];
    const void* mask = d_in[1];
    if (n_in >= 2 && in_sizes[0] < in_sizes[1]) {
        emb = (const float*)d_in[1];
        mask = d_in[0];
    }
    float* out = (float*)d_out;

    cudaFuncSetAttribute(gemm_kernel, cudaFuncAttributeMaxDynamicSharedMemorySize, SMEM_DYN);

    decode_kernel<<<1, 1024>>>((const unsigned*)mask);
    normalize_kernel<<<BB * NN, 256>>>(emb);
    gemm_kernel<<<dim3(528, BB), 256, SMEM_DYN>>>(out);
    median_kernel<<<BB, 1024>>>(out);
    match_kernel<<<BB * NN, 256>>>(out);
}